// round 7
// baseline (speedup 1.0000x reference)
#include <cuda_runtime.h>
#include <math.h>

#define Dn   64
#define Rn   4
#define NMAX 100000
#define EMAX 1200000
#define SEGS (NMAX * Rn)
#define BSTR 68    // weight smem stride: banks (2q*68)%32 = 8q -> conflict-free permuted B frags
#define CNPB 128   // conv nodes per block
#define SUSTR 264  // su stride: (g*264+2q)%32 = (8g+2q)%32 -> conflict-free per LDS.64 phase

// ---------------- scratch ----------------
__device__ int   g_off[SEGS + 1];
__device__ int   g_cur[SEGS];
__device__ int   g_srcs[EMAX];
__device__ int   g_part[512];
__device__ float g_h1[(size_t)NMAX * Dn];
__device__ float g_g1[(size_t)NMAX * Dn];
__device__ float g_h2[(size_t)NMAX * Dn];

__device__ __forceinline__ float sigmoidf_(float v) {
    return 1.0f / (1.0f + __expf(-v));
}

__device__ __forceinline__ unsigned f2tf32(float f) {
    unsigned u;
    asm("cvt.rna.tf32.f32 %0, %1;" : "=r"(u) : "f"(f));
    return u;
}

__device__ __forceinline__ void mma_tf32(float d[4], const unsigned a[4], const unsigned b[2]) {
    asm volatile("mma.sync.aligned.m16n8k8.row.col.f32.tf32.tf32.f32 "
                 "{%0,%1,%2,%3}, {%4,%5,%6,%7}, {%8,%9}, {%0,%1,%2,%3};"
                 : "+f"(d[0]), "+f"(d[1]), "+f"(d[2]), "+f"(d[3])
                 : "r"(a[0]), "r"(a[1]), "r"(a[2]), "r"(a[3]), "r"(b[0]), "r"(b[1]));
}

// ---------------- CSR build ----------------
__global__ void zero_deg_kernel() {
    int i = blockIdx.x * blockDim.x + threadIdx.x;
    if (i < SEGS) g_cur[i] = 0;
}

__global__ void hist_kernel(const int* __restrict__ dst, const int* __restrict__ rel, int E) {
    int e = blockIdx.x * blockDim.x + threadIdx.x;
    if (e < E) atomicAdd(&g_cur[dst[e] * Rn + rel[e]], 1);
}

__global__ void __launch_bounds__(1024) scan1_kernel(int n) {
    __shared__ int wsum[32];
    int i = blockIdx.x * 1024 + threadIdx.x;
    int lane = threadIdx.x & 31, wid = threadIdx.x >> 5;
    int v = (i < n) ? g_cur[i] : 0;
    int s = v;
#pragma unroll
    for (int d = 1; d < 32; d <<= 1) {
        int t = __shfl_up_sync(0xffffffffu, s, d);
        if (lane >= d) s += t;
    }
    if (lane == 31) wsum[wid] = s;
    __syncthreads();
    if (wid == 0) {
        int t = wsum[lane];
#pragma unroll
        for (int d = 1; d < 32; d <<= 1) {
            int u = __shfl_up_sync(0xffffffffu, t, d);
            if (lane >= d) t += u;
        }
        wsum[lane] = t;
    }
    __syncthreads();
    int add = (wid > 0) ? wsum[wid - 1] : 0;
    int inc = s + add;
    if (i < n) g_off[i] = inc - v;
    if (threadIdx.x == 1023) g_part[blockIdx.x] = inc;
}

__global__ void __launch_bounds__(512) scan2_kernel(int n) {
    __shared__ int wsum[16];
    int i = threadIdx.x;
    int lane = i & 31, wid = i >> 5;
    int v = (i < n) ? g_part[i] : 0;
    int s = v;
#pragma unroll
    for (int d = 1; d < 32; d <<= 1) {
        int t = __shfl_up_sync(0xffffffffu, s, d);
        if (lane >= d) s += t;
    }
    if (lane == 31) wsum[wid] = s;
    __syncthreads();
    if (wid == 0 && lane < 16) {
        int t = wsum[lane];
#pragma unroll
        for (int d = 1; d < 16; d <<= 1) {
            int u = __shfl_up_sync(0x0000ffffu, t, d);
            if (lane >= d) t += u;
        }
        wsum[lane] = t;
    }
    __syncthreads();
    int add = (wid > 0) ? wsum[wid - 1] : 0;
    if (i < n) g_part[i] = s - v + add;
}

__global__ void scan3_kernel(int n, int E) {
    int i = blockIdx.x * blockDim.x + threadIdx.x;
    if (i < n) {
        int o = g_off[i] + g_part[i >> 10];
        g_off[i] = o;
        g_cur[i] = o;
    }
    if (i == 0) g_off[n] = E;
}

__global__ void scatter_kernel(const int* __restrict__ src, const int* __restrict__ dst,
                               const int* __restrict__ rel, int E) {
    int e = blockIdx.x * blockDim.x + threadIdx.x;
    if (e >= E) return;
    int seg = dst[e] * Rn + rel[e];
    int p = atomicAdd(&g_cur[seg], 1);
    g_srcs[p] = src[e];
}

// ---------------- fused conv: smem aggregation + tf32 mma + bias + sigmoid ----------------
// 256 threads / 8 warps, 128 nodes/block, warp -> one m16 tile (16 nodes).
// Phase 1: gather-mean each of the block's 512 (node,rel) segments into smem.
// Phase 2: mma over [S_mean(256) | x(64)] with permuted-k fragments.
__global__ void __launch_bounds__(256)
conv_fused_kernel(const float* __restrict__ xin,
                  const float* __restrict__ w,   // [64][256]
                  const float* __restrict__ b,
                  const float* __restrict__ ws,  // [64][64]
                  const float* __restrict__ bs,
                  float* __restrict__ out,
                  int N) {
    extern __shared__ unsigned smu[];
    unsigned* sw = smu;                             // 320 * BSTR words
    float* su = (float*)(smu + 320 * BSTR);         // CNPB * SUSTR floats
    float* sb = su + CNPB * SUSTR;                  // 64
    int tid = threadIdx.x;

    // stage weights transposed: sw[k][j]; rows 256..319 = self-loop ws
    for (int idx = tid; idx < Dn * 256; idx += 256) {
        int j = idx >> 8, k = idx & 255;
        sw[k * BSTR + j] = f2tf32(w[idx]);
    }
    for (int idx = tid; idx < Dn * Dn; idx += 256) {
        int j = idx >> 6, k = idx & 63;
        sw[(256 + k) * BSTR + j] = f2tf32(ws[idx]);
    }
    if (tid < Dn) sb[tid] = b[tid] + bs[tid];

    int base = blockIdx.x * CNPB;

    // ---- phase 1: aggregate 512 local segments into su ----
    int grp = tid >> 4, l16 = tid & 15;
#pragma unroll 1
    for (int it = 0; it < (CNPB * Rn) / 16; it++) {
        int segl = it * 16 + grp;              // local segment 0..511
        int n = segl >> 2, r = segl & 3;
        int node = base + n;
        float4 acc = make_float4(0.f, 0.f, 0.f, 0.f);
        if (node < N) {
            int seg = node * Rn + r;
            int e0 = __ldg(&g_off[seg]);
            int e1 = __ldg(&g_off[seg + 1]);
            int e = e0;
            for (; e + 1 < e1; e += 2) {
                int s0 = __ldg(&g_srcs[e]);
                int s1 = __ldg(&g_srcs[e + 1]);
                float4 v0 = *reinterpret_cast<const float4*>(xin + (size_t)s0 * Dn + l16 * 4);
                float4 v1 = *reinterpret_cast<const float4*>(xin + (size_t)s1 * Dn + l16 * 4);
                acc.x += v0.x + v1.x; acc.y += v0.y + v1.y;
                acc.z += v0.z + v1.z; acc.w += v0.w + v1.w;
            }
            if (e < e1) {
                int s0 = __ldg(&g_srcs[e]);
                float4 v0 = *reinterpret_cast<const float4*>(xin + (size_t)s0 * Dn + l16 * 4);
                acc.x += v0.x; acc.y += v0.y; acc.z += v0.z; acc.w += v0.w;
            }
            int d = e1 - e0;
            float inv = 1.0f / (float)(d > 1 ? d : 1);
            acc.x *= inv; acc.y *= inv; acc.z *= inv; acc.w *= inv;
        }
        *reinterpret_cast<float4*>(su + n * SUSTR + r * Dn + l16 * 4) = acc;
    }
    __syncthreads();

    // ---- phase 2: mma ----
    int lane = tid & 31, warp = tid >> 5;
    int g = lane >> 2, q = lane & 3;
    int lw0 = warp * 16 + g, lw1 = lw0 + 8;      // local node rows of the m16 tile
    int r0 = base + lw0, r1 = base + lw1;
    int cr0 = min(r0, N - 1), cr1 = min(r1, N - 1);

    float acc[8][4];
#pragma unroll
    for (int n = 0; n < 8; n++)
#pragma unroll
        for (int i = 0; i < 4; i++) acc[n][i] = 0.f;

    const float* su0 = su + lw0 * SUSTR;
    const float* su1 = su + lw1 * SUSTR;

#pragma unroll 4
    for (int ks = 0; ks < 32; ks++) {
        int ka = ks * 8 + 2 * q;
        float2 s0 = *reinterpret_cast<const float2*>(su0 + ka);
        float2 s1 = *reinterpret_cast<const float2*>(su1 + ka);
        unsigned a[4] = { f2tf32(s0.x), f2tf32(s1.x), f2tf32(s0.y), f2tf32(s1.y) };
        const unsigned* w0 = sw + ka * BSTR + g;
#pragma unroll
        for (int n = 0; n < 8; n++) {
            unsigned bb[2] = { w0[n * 8], w0[BSTR + n * 8] };
            mma_tf32(acc[n], a, bb);
        }
    }

    const float* X0 = xin + (size_t)cr0 * Dn;
    const float* X1 = xin + (size_t)cr1 * Dn;
#pragma unroll
    for (int ks = 0; ks < 8; ks++) {
        int ka = ks * 8 + 2 * q;
        float2 s0 = *reinterpret_cast<const float2*>(X0 + ka);
        float2 s1 = *reinterpret_cast<const float2*>(X1 + ka);
        unsigned a[4] = { f2tf32(s0.x), f2tf32(s1.x), f2tf32(s0.y), f2tf32(s1.y) };
        const unsigned* w0 = sw + (256 + ka) * BSTR + g;
#pragma unroll
        for (int n = 0; n < 8; n++) {
            unsigned bb[2] = { w0[n * 8], w0[BSTR + n * 8] };
            mma_tf32(acc[n], a, bb);
        }
    }

#pragma unroll
    for (int n = 0; n < 8; n++) {
        int col = n * 8 + 2 * q;
        float b0v = sb[col], b1v = sb[col + 1];
        if (r0 < N) {
            float2 o = { sigmoidf_(acc[n][0] + b0v), sigmoidf_(acc[n][1] + b1v) };
            *reinterpret_cast<float2*>(out + (size_t)r0 * Dn + col) = o;
        }
        if (r1 < N) {
            float2 o = { sigmoidf_(acc[n][2] + b0v), sigmoidf_(acc[n][3] + b1v) };
            *reinterpret_cast<float2*>(out + (size_t)r1 * Dn + col) = o;
        }
    }
}

// ---------------- highway via tf32 mma ----------------
// 256 threads / 8 warps, 16 nodes per warp -> 128 nodes per block.
__global__ void __launch_bounds__(256)
highway_mma_kernel(const float* __restrict__ h,
                   const float* __restrict__ prev,
                   const float* __restrict__ pw,   // [64][128]
                   const float* __restrict__ pb,
                   const float* __restrict__ tw,   // [64][128]
                   const float* __restrict__ tb,
                   float* __restrict__ out,
                   int N) {
    extern __shared__ unsigned smu[];
    unsigned* sp = smu;                            // 128 * BSTR
    unsigned* st = sp + 128 * BSTR;                // 128 * BSTR
    float* sbp = (float*)(st + 128 * BSTR);        // 64
    float* sbt = sbp + Dn;                         // 64
    int tid = threadIdx.x;

    for (int idx = tid; idx < Dn * 128; idx += 256) {
        int j = idx >> 7, k = idx & 127;
        sp[k * BSTR + j] = f2tf32(pw[idx]);
        st[k * BSTR + j] = f2tf32(tw[idx]);
    }
    if (tid < Dn) { sbp[tid] = pb[tid]; sbt[tid] = tb[tid]; }
    __syncthreads();

    int lane = tid & 31, warp = tid >> 5;
    int g = lane >> 2, q = lane & 3;
    int mbase = blockIdx.x * 128 + warp * 16;

    int r0 = mbase + g, r1 = r0 + 8;
    int cr0 = min(r0, N - 1), cr1 = min(r1, N - 1);

    float accP[8][4], accT[8][4];
#pragma unroll
    for (int n = 0; n < 8; n++)
#pragma unroll
        for (int i = 0; i < 4; i++) { accP[n][i] = 0.f; accT[n][i] = 0.f; }

    const float* H0 = h + (size_t)cr0 * Dn;
    const float* H1 = h + (size_t)cr1 * Dn;
    const float* P0 = prev + (size_t)cr0 * Dn;
    const float* P1 = prev + (size_t)cr1 * Dn;

#pragma unroll
    for (int ks = 0; ks < 8; ks++) {
        int ka = ks * 8 + 2 * q;
        float2 s0 = *reinterpret_cast<const float2*>(H0 + ka);
        float2 s1 = *reinterpret_cast<const float2*>(H1 + ka);
        unsigned a[4] = { f2tf32(s0.x), f2tf32(s1.x), f2tf32(s0.y), f2tf32(s1.y) };
        const unsigned* p0 = sp + ka * BSTR + g;
        const unsigned* t0 = st + ka * BSTR + g;
#pragma unroll
        for (int n = 0; n < 8; n++) {
            unsigned bp[2] = { p0[n * 8], p0[BSTR + n * 8] };
            unsigned bt[2] = { t0[n * 8], t0[BSTR + n * 8] };
            mma_tf32(accP[n], a, bp);
            mma_tf32(accT[n], a, bt);
        }
    }
#pragma unroll
    for (int ks = 0; ks < 8; ks++) {
        int ka = ks * 8 + 2 * q;
        float2 s0 = *reinterpret_cast<const float2*>(P0 + ka);
        float2 s1 = *reinterpret_cast<const float2*>(P1 + ka);
        unsigned a[4] = { f2tf32(s0.x), f2tf32(s1.x), f2tf32(s0.y), f2tf32(s1.y) };
        const unsigned* p0 = sp + (64 + ka) * BSTR + g;
        const unsigned* t0 = st + (64 + ka) * BSTR + g;
#pragma unroll
        for (int n = 0; n < 8; n++) {
            unsigned bp[2] = { p0[n * 8], p0[BSTR + n * 8] };
            unsigned bt[2] = { t0[n * 8], t0[BSTR + n * 8] };
            mma_tf32(accP[n], a, bp);
            mma_tf32(accT[n], a, bt);
        }
    }

#pragma unroll
    for (int n = 0; n < 8; n++) {
        int col = n * 8 + 2 * q;
        float bp0 = sbp[col], bp1 = sbp[col + 1];
        float bt0 = sbt[col], bt1 = sbt[col + 1];
        if (r0 < N) {
            float2 hv = *reinterpret_cast<const float2*>(h + (size_t)r0 * Dn + col);
            float pr0 = fmaxf(accP[n][0] + bp0, 0.f);
            float pr1 = fmaxf(accP[n][1] + bp1, 0.f);
            float g0 = sigmoidf_(accT[n][0] + bt0);
            float g1 = sigmoidf_(accT[n][1] + bt1);
            float2 o = { g0 * pr0 + (1.f - g0) * hv.x, g1 * pr1 + (1.f - g1) * hv.y };
            *reinterpret_cast<float2*>(out + (size_t)r0 * Dn + col) = o;
        }
        if (r1 < N) {
            float2 hv = *reinterpret_cast<const float2*>(h + (size_t)r1 * Dn + col);
            float pr0 = fmaxf(accP[n][2] + bp0, 0.f);
            float pr1 = fmaxf(accP[n][3] + bp1, 0.f);
            float g0 = sigmoidf_(accT[n][2] + bt0);
            float g1 = sigmoidf_(accT[n][3] + bt1);
            float2 o = { g0 * pr0 + (1.f - g0) * hv.x, g1 * pr1 + (1.f - g1) * hv.y };
            *reinterpret_cast<float2*>(out + (size_t)r1 * Dn + col) = o;
        }
    }
}

// ---------------- launch ----------------
extern "C" void kernel_launch(void* const* d_in, const int* in_sizes, int n_in,
                              void* d_out, int out_size) {
    const float* x    = (const float*)d_in[0];
    const int*   src  = (const int*)d_in[1];
    const int*   dst  = (const int*)d_in[2];
    const int*   rel  = (const int*)d_in[3];
    const float* c1w  = (const float*)d_in[4];
    const float* c1b  = (const float*)d_in[5];
    const float* c1ws = (const float*)d_in[6];
    const float* c1bs = (const float*)d_in[7];
    const float* h1pw = (const float*)d_in[8];
    const float* h1pb = (const float*)d_in[9];
    const float* h1tw = (const float*)d_in[10];
    const float* h1tb = (const float*)d_in[11];
    const float* c2w  = (const float*)d_in[12];
    const float* c2b  = (const float*)d_in[13];
    const float* c2ws = (const float*)d_in[14];
    const float* c2bs = (const float*)d_in[15];
    const float* h2pw = (const float*)d_in[16];
    const float* h2pb = (const float*)d_in[17];
    const float* h2tw = (const float*)d_in[18];
    const float* h2tb = (const float*)d_in[19];
    float* out = (float*)d_out;

    int N = in_sizes[0] / Dn;
    int E = in_sizes[1];

    float *h1p, *g1p, *h2p;
    cudaGetSymbolAddress((void**)&h1p, g_h1);
    cudaGetSymbolAddress((void**)&g1p, g_g1);
    cudaGetSymbolAddress((void**)&h2p, g_h2);

    const int convSmem = (320 * BSTR + CNPB * SUSTR + 64) * 4;
    const int hwSmem   = 2 * 128 * BSTR * 4 + 128 * 4;
    cudaFuncSetAttribute(conv_fused_kernel, cudaFuncAttributeMaxDynamicSharedMemorySize, convSmem);
    cudaFuncSetAttribute(highway_mma_kernel, cudaFuncAttributeMaxDynamicSharedMemorySize, hwSmem);

    int convGrid = (N + CNPB - 1) / CNPB;
    int hwGrid   = (N + 127) / 128;
    int scanBlocks = (SEGS + 1023) / 1024;

    // ---- CSR build (graph identical in both layers) ----
    zero_deg_kernel<<<(SEGS + 255) / 256, 256>>>();
    hist_kernel<<<(E + 255) / 256, 256>>>(dst, rel, E);
    scan1_kernel<<<scanBlocks, 1024>>>(SEGS);
    scan2_kernel<<<1, 512>>>(scanBlocks);
    scan3_kernel<<<(SEGS + 255) / 256, 256>>>(SEGS, E);
    scatter_kernel<<<(E + 255) / 256, 256>>>(src, dst, rel, E);

    // ---- layer 1 ----
    conv_fused_kernel<<<convGrid, 256, convSmem>>>(x, c1w, c1b, c1ws, c1bs, h1p, N);
    highway_mma_kernel<<<hwGrid, 256, hwSmem>>>(h1p, x, h1pw, h1pb, h1tw, h1tb, g1p, N);

    // ---- layer 2 ----
    conv_fused_kernel<<<convGrid, 256, convSmem>>>(g1p, c2w, c2b, c2ws, c2bs, h2p, N);
    highway_mma_kernel<<<hwGrid, 256, hwSmem>>>(h2p, h1p, h2pw, h2pb, h2tw, h2tb, out, N);
}

// round 8
// speedup vs baseline: 2.0294x; 2.0294x over previous
#include <cuda_runtime.h>
#include <cuda_bf16.h>
#include <math.h>

#define Dn   64
#define Rn   4
#define NMAX 100000
#define EMAX 1200000
#define SEGS (NMAX * Rn)
#define BSTR 68   // weight smem stride: banks (2q*68)%32 = 8q -> conflict-free permuted B frags

// ---------------- scratch ----------------
__device__ int   g_deg[SEGS];
__device__ int   g_off[SEGS + 1];
__device__ int   g_cur[SEGS];
__device__ int   g_srcs[EMAX];
__device__ int   g_part[512];
__device__ __nv_bfloat162 g_S[(size_t)SEGS * (Dn / 2)];  // per-(node,rel) MEAN, bf16
__device__ float g_h1[(size_t)NMAX * Dn];
__device__ float g_g1[(size_t)NMAX * Dn];
__device__ float g_h2[(size_t)NMAX * Dn];

__device__ __forceinline__ float sigmoidf_(float v) {
    return 1.0f / (1.0f + __expf(-v));
}

__device__ __forceinline__ unsigned f2tf32(float f) {
    unsigned u;
    asm("cvt.rna.tf32.f32 %0, %1;" : "=r"(u) : "f"(f));
    return u;
}

__device__ __forceinline__ void mma_tf32(float d[4], const unsigned a[4], const unsigned b[2]) {
    asm volatile("mma.sync.aligned.m16n8k8.row.col.f32.tf32.tf32.f32 "
                 "{%0,%1,%2,%3}, {%4,%5,%6,%7}, {%8,%9}, {%0,%1,%2,%3};"
                 : "+f"(d[0]), "+f"(d[1]), "+f"(d[2]), "+f"(d[3])
                 : "r"(a[0]), "r"(a[1]), "r"(a[2]), "r"(a[3]), "r"(b[0]), "r"(b[1]));
}

// ---------------- CSR build ----------------
__global__ void zero_deg_kernel() {
    int i = blockIdx.x * blockDim.x + threadIdx.x;
    if (i < SEGS) g_deg[i] = 0;
}

__global__ void hist_kernel(const int* __restrict__ dst, const int* __restrict__ rel, int E) {
    int e = blockIdx.x * blockDim.x + threadIdx.x;
    if (e < E) atomicAdd(&g_deg[dst[e] * Rn + rel[e]], 1);
}

__global__ void __launch_bounds__(1024) scan1_kernel(int n) {
    __shared__ int wsum[32];
    int i = blockIdx.x * 1024 + threadIdx.x;
    int lane = threadIdx.x & 31, wid = threadIdx.x >> 5;
    int v = (i < n) ? g_deg[i] : 0;
    int s = v;
#pragma unroll
    for (int d = 1; d < 32; d <<= 1) {
        int t = __shfl_up_sync(0xffffffffu, s, d);
        if (lane >= d) s += t;
    }
    if (lane == 31) wsum[wid] = s;
    __syncthreads();
    if (wid == 0) {
        int t = wsum[lane];
#pragma unroll
        for (int d = 1; d < 32; d <<= 1) {
            int u = __shfl_up_sync(0xffffffffu, t, d);
            if (lane >= d) t += u;
        }
        wsum[lane] = t;
    }
    __syncthreads();
    int add = (wid > 0) ? wsum[wid - 1] : 0;
    int inc = s + add;
    if (i < n) g_off[i] = inc - v;
    if (threadIdx.x == 1023) g_part[blockIdx.x] = inc;
}

__global__ void __launch_bounds__(512) scan2_kernel(int n) {
    __shared__ int wsum[16];
    int i = threadIdx.x;
    int lane = i & 31, wid = i >> 5;
    int v = (i < n) ? g_part[i] : 0;
    int s = v;
#pragma unroll
    for (int d = 1; d < 32; d <<= 1) {
        int t = __shfl_up_sync(0xffffffffu, s, d);
        if (lane >= d) s += t;
    }
    if (lane == 31) wsum[wid] = s;
    __syncthreads();
    if (wid == 0 && lane < 16) {
        int t = wsum[lane];
#pragma unroll
        for (int d = 1; d < 16; d <<= 1) {
            int u = __shfl_up_sync(0x0000ffffu, t, d);
            if (lane >= d) t += u;
        }
        wsum[lane] = t;
    }
    __syncthreads();
    int add = (wid > 0) ? wsum[wid - 1] : 0;
    if (i < n) g_part[i] = s - v + add;
}

__global__ void scan3_kernel(int n, int E) {
    int i = blockIdx.x * blockDim.x + threadIdx.x;
    if (i < n) {
        int o = g_off[i] + g_part[i >> 10];
        g_off[i] = o;
        g_cur[i] = o;
    }
    if (i == 0) g_off[n] = E;
}

__global__ void scatter_kernel(const int* __restrict__ src, const int* __restrict__ dst,
                               const int* __restrict__ rel, int E) {
    int e = blockIdx.x * blockDim.x + threadIdx.x;
    if (e >= E) return;
    int seg = dst[e] * Rn + rel[e];
    int p = atomicAdd(&g_cur[seg], 1);
    g_srcs[p] = src[e];
}

// ---------------- aggregate: S[seg] = MEAN over edges of x[src], bf16 out ----------------
__global__ void __launch_bounds__(256) aggregate_kernel(const float* __restrict__ x) {
    int t = blockIdx.x * 256 + threadIdx.x;
    int seg = t >> 4;
    int lane = t & 15;
    if (seg >= SEGS) return;
    int e0 = __ldg(&g_off[seg]);
    int e1 = __ldg(&g_off[seg + 1]);
    float4 acc = make_float4(0.f, 0.f, 0.f, 0.f);
    int e = e0;
    for (; e + 3 < e1; e += 4) {
        int s0 = __ldg(&g_srcs[e]);
        int s1 = __ldg(&g_srcs[e + 1]);
        int s2 = __ldg(&g_srcs[e + 2]);
        int s3 = __ldg(&g_srcs[e + 3]);
        float4 v0 = *reinterpret_cast<const float4*>(x + (size_t)s0 * Dn + lane * 4);
        float4 v1 = *reinterpret_cast<const float4*>(x + (size_t)s1 * Dn + lane * 4);
        float4 v2 = *reinterpret_cast<const float4*>(x + (size_t)s2 * Dn + lane * 4);
        float4 v3 = *reinterpret_cast<const float4*>(x + (size_t)s3 * Dn + lane * 4);
        acc.x += (v0.x + v1.x) + (v2.x + v3.x);
        acc.y += (v0.y + v1.y) + (v2.y + v3.y);
        acc.z += (v0.z + v1.z) + (v2.z + v3.z);
        acc.w += (v0.w + v1.w) + (v2.w + v3.w);
    }
    for (; e < e1; e++) {
        int s0 = __ldg(&g_srcs[e]);
        float4 v0 = *reinterpret_cast<const float4*>(x + (size_t)s0 * Dn + lane * 4);
        acc.x += v0.x; acc.y += v0.y; acc.z += v0.z; acc.w += v0.w;
    }
    int d = e1 - e0;
    float inv = 1.0f / (float)(d > 1 ? d : 1);
    __nv_bfloat162 p0 = __float22bfloat162_rn(make_float2(acc.x * inv, acc.y * inv));
    __nv_bfloat162 p1 = __float22bfloat162_rn(make_float2(acc.z * inv, acc.w * inv));
    g_S[(size_t)seg * 32 + lane * 2]     = p0;
    g_S[(size_t)seg * 32 + lane * 2 + 1] = p1;
}

// ---------------- conv via tf32 mma: out = sigmoid([S_mean | x] @ W^T + b) ----------------
// 256 threads / 8 warps, 32 nodes per warp -> 256 nodes per block.
// Permuted-k frags: logical q <-> actual k0+2q, logical q+4 <-> actual k0+2q+1.
__global__ void __launch_bounds__(256)
conv_mma_kernel(const float* __restrict__ xin,
                const __nv_bfloat162* __restrict__ S,
                const float* __restrict__ w,   // [64][256]
                const float* __restrict__ b,
                const float* __restrict__ ws,  // [64][64]
                const float* __restrict__ bs,
                float* __restrict__ out,
                int N) {
    extern __shared__ unsigned smu[];
    unsigned* sw = smu;                           // 320 * BSTR words
    float* sb = (float*)(smu + 320 * BSTR);       // 64
    int tid = threadIdx.x;

    for (int idx = tid; idx < Dn * 256; idx += 256) {
        int j = idx >> 8, k = idx & 255;
        sw[k * BSTR + j] = f2tf32(w[idx]);
    }
    for (int idx = tid; idx < Dn * Dn; idx += 256) {
        int j = idx >> 6, k = idx & 63;
        sw[(256 + k) * BSTR + j] = f2tf32(ws[idx]);
    }
    if (tid < Dn) sb[tid] = b[tid] + bs[tid];
    __syncthreads();

    int lane = tid & 31, warp = tid >> 5;
    int g = lane >> 2, q = lane & 3;
    int mbase = blockIdx.x * 256 + warp * 32;

    int r0 = mbase + g, r1 = r0 + 8, r2 = r0 + 16, r3 = r0 + 24;
    int cr0 = min(r0, N - 1), cr1 = min(r1, N - 1);
    int cr2 = min(r2, N - 1), cr3 = min(r3, N - 1);

    float acc[2][8][4];
#pragma unroll
    for (int mt = 0; mt < 2; mt++)
#pragma unroll
        for (int n = 0; n < 8; n++)
#pragma unroll
            for (int i = 0; i < 4; i++) acc[mt][n][i] = 0.f;

    const __nv_bfloat162* S0 = S + (size_t)cr0 * 128;
    const __nv_bfloat162* S1 = S + (size_t)cr1 * 128;
    const __nv_bfloat162* S2 = S + (size_t)cr2 * 128;
    const __nv_bfloat162* S3 = S + (size_t)cr3 * 128;

#pragma unroll 4
    for (int ks = 0; ks < 32; ks++) {
        int pi = ks * 4 + q;   // bf16x2 pair index: elements 2q, 2q+1 of k-block
        float2 s0 = __bfloat1622float2(S0[pi]);
        float2 s1 = __bfloat1622float2(S1[pi]);
        float2 s2 = __bfloat1622float2(S2[pi]);
        float2 s3 = __bfloat1622float2(S3[pi]);
        unsigned a0[4] = { f2tf32(s0.x), f2tf32(s1.x), f2tf32(s0.y), f2tf32(s1.y) };
        unsigned a1[4] = { f2tf32(s2.x), f2tf32(s3.x), f2tf32(s2.y), f2tf32(s3.y) };
        const unsigned* w0 = sw + (ks * 8 + 2 * q) * BSTR + g;
#pragma unroll
        for (int n = 0; n < 8; n++) {
            unsigned bb[2] = { w0[n * 8], w0[BSTR + n * 8] };
            mma_tf32(acc[0][n], a0, bb);
            mma_tf32(acc[1][n], a1, bb);
        }
    }

    const float* X0 = xin + (size_t)cr0 * Dn;
    const float* X1 = xin + (size_t)cr1 * Dn;
    const float* X2 = xin + (size_t)cr2 * Dn;
    const float* X3 = xin + (size_t)cr3 * Dn;
#pragma unroll
    for (int ks = 0; ks < 8; ks++) {
        int ka = ks * 8 + 2 * q;
        float2 s0 = *reinterpret_cast<const float2*>(X0 + ka);
        float2 s1 = *reinterpret_cast<const float2*>(X1 + ka);
        float2 s2 = *reinterpret_cast<const float2*>(X2 + ka);
        float2 s3 = *reinterpret_cast<const float2*>(X3 + ka);
        unsigned a0[4] = { f2tf32(s0.x), f2tf32(s1.x), f2tf32(s0.y), f2tf32(s1.y) };
        unsigned a1[4] = { f2tf32(s2.x), f2tf32(s3.x), f2tf32(s2.y), f2tf32(s3.y) };
        const unsigned* w0 = sw + (256 + ka) * BSTR + g;
#pragma unroll
        for (int n = 0; n < 8; n++) {
            unsigned bb[2] = { w0[n * 8], w0[BSTR + n * 8] };
            mma_tf32(acc[0][n], a0, bb);
            mma_tf32(acc[1][n], a1, bb);
        }
    }

#pragma unroll
    for (int n = 0; n < 8; n++) {
        int col = n * 8 + 2 * q;
        float b0v = sb[col], b1v = sb[col + 1];
        if (r0 < N) {
            float2 o = { sigmoidf_(acc[0][n][0] + b0v), sigmoidf_(acc[0][n][1] + b1v) };
            *reinterpret_cast<float2*>(out + (size_t)r0 * Dn + col) = o;
        }
        if (r1 < N) {
            float2 o = { sigmoidf_(acc[0][n][2] + b0v), sigmoidf_(acc[0][n][3] + b1v) };
            *reinterpret_cast<float2*>(out + (size_t)r1 * Dn + col) = o;
        }
        if (r2 < N) {
            float2 o = { sigmoidf_(acc[1][n][0] + b0v), sigmoidf_(acc[1][n][1] + b1v) };
            *reinterpret_cast<float2*>(out + (size_t)r2 * Dn + col) = o;
        }
        if (r3 < N) {
            float2 o = { sigmoidf_(acc[1][n][2] + b0v), sigmoidf_(acc[1][n][3] + b1v) };
            *reinterpret_cast<float2*>(out + (size_t)r3 * Dn + col) = o;
        }
    }
}

// ---------------- highway via tf32 mma ----------------
// 256 threads / 8 warps, 16 nodes per warp -> 128 nodes per block.
__global__ void __launch_bounds__(256)
highway_mma_kernel(const float* __restrict__ h,
                   const float* __restrict__ prev,
                   const float* __restrict__ pw,   // [64][128]
                   const float* __restrict__ pb,
                   const float* __restrict__ tw,   // [64][128]
                   const float* __restrict__ tb,
                   float* __restrict__ out,
                   int N) {
    extern __shared__ unsigned smu[];
    unsigned* sp = smu;                            // 128 * BSTR
    unsigned* st = sp + 128 * BSTR;                // 128 * BSTR
    float* sbp = (float*)(st + 128 * BSTR);        // 64
    float* sbt = sbp + Dn;                         // 64
    int tid = threadIdx.x;

    for (int idx = tid; idx < Dn * 128; idx += 256) {
        int j = idx >> 7, k = idx & 127;
        sp[k * BSTR + j] = f2tf32(pw[idx]);
        st[k * BSTR + j] = f2tf32(tw[idx]);
    }
    if (tid < Dn) { sbp[tid] = pb[tid]; sbt[tid] = tb[tid]; }
    __syncthreads();

    int lane = tid & 31, warp = tid >> 5;
    int g = lane >> 2, q = lane & 3;
    int mbase = blockIdx.x * 128 + warp * 16;

    int r0 = mbase + g, r1 = r0 + 8;
    int cr0 = min(r0, N - 1), cr1 = min(r1, N - 1);

    float accP[8][4], accT[8][4];
#pragma unroll
    for (int n = 0; n < 8; n++)
#pragma unroll
        for (int i = 0; i < 4; i++) { accP[n][i] = 0.f; accT[n][i] = 0.f; }

    const float* H0 = h + (size_t)cr0 * Dn;
    const float* H1 = h + (size_t)cr1 * Dn;
    const float* P0 = prev + (size_t)cr0 * Dn;
    const float* P1 = prev + (size_t)cr1 * Dn;

#pragma unroll
    for (int ks = 0; ks < 8; ks++) {
        int ka = ks * 8 + 2 * q;
        float2 s0 = *reinterpret_cast<const float2*>(H0 + ka);
        float2 s1 = *reinterpret_cast<const float2*>(H1 + ka);
        unsigned a[4] = { f2tf32(s0.x), f2tf32(s1.x), f2tf32(s0.y), f2tf32(s1.y) };
        const unsigned* p0 = sp + ka * BSTR + g;
        const unsigned* t0 = st + ka * BSTR + g;
#pragma unroll
        for (int n = 0; n < 8; n++) {
            unsigned bp[2] = { p0[n * 8], p0[BSTR + n * 8] };
            unsigned bt[2] = { t0[n * 8], t0[BSTR + n * 8] };
            mma_tf32(accP[n], a, bp);
            mma_tf32(accT[n], a, bt);
        }
    }
#pragma unroll
    for (int ks = 0; ks < 8; ks++) {
        int ka = ks * 8 + 2 * q;
        float2 s0 = *reinterpret_cast<const float2*>(P0 + ka);
        float2 s1 = *reinterpret_cast<const float2*>(P1 + ka);
        unsigned a[4] = { f2tf32(s0.x), f2tf32(s1.x), f2tf32(s0.y), f2tf32(s1.y) };
        const unsigned* p0 = sp + (64 + ka) * BSTR + g;
        const unsigned* t0 = st + (64 + ka) * BSTR + g;
#pragma unroll
        for (int n = 0; n < 8; n++) {
            unsigned bp[2] = { p0[n * 8], p0[BSTR + n * 8] };
            unsigned bt[2] = { t0[n * 8], t0[BSTR + n * 8] };
            mma_tf32(accP[n], a, bp);
            mma_tf32(accT[n], a, bt);
        }
    }

#pragma unroll
    for (int n = 0; n < 8; n++) {
        int col = n * 8 + 2 * q;
        float bp0 = sbp[col], bp1 = sbp[col + 1];
        float bt0 = sbt[col], bt1 = sbt[col + 1];
        if (r0 < N) {
            float2 hv = *reinterpret_cast<const float2*>(h + (size_t)r0 * Dn + col);
            float pr0 = fmaxf(accP[n][0] + bp0, 0.f);
            float pr1 = fmaxf(accP[n][1] + bp1, 0.f);
            float g0 = sigmoidf_(accT[n][0] + bt0);
            float g1 = sigmoidf_(accT[n][1] + bt1);
            float2 o = { g0 * pr0 + (1.f - g0) * hv.x, g1 * pr1 + (1.f - g1) * hv.y };
            *reinterpret_cast<float2*>(out + (size_t)r0 * Dn + col) = o;
        }
        if (r1 < N) {
            float2 hv = *reinterpret_cast<const float2*>(h + (size_t)r1 * Dn + col);
            float pr0 = fmaxf(accP[n][2] + bp0, 0.f);
            float pr1 = fmaxf(accP[n][3] + bp1, 0.f);
            float g0 = sigmoidf_(accT[n][2] + bt0);
            float g1 = sigmoidf_(accT[n][3] + bt1);
            float2 o = { g0 * pr0 + (1.f - g0) * hv.x, g1 * pr1 + (1.f - g1) * hv.y };
            *reinterpret_cast<float2*>(out + (size_t)r1 * Dn + col) = o;
        }
    }
}

// ---------------- launch ----------------
extern "C" void kernel_launch(void* const* d_in, const int* in_sizes, int n_in,
                              void* d_out, int out_size) {
    const float* x    = (const float*)d_in[0];
    const int*   src  = (const int*)d_in[1];
    const int*   dst  = (const int*)d_in[2];
    const int*   rel  = (const int*)d_in[3];
    const float* c1w  = (const float*)d_in[4];
    const float* c1b  = (const float*)d_in[5];
    const float* c1ws = (const float*)d_in[6];
    const float* c1bs = (const float*)d_in[7];
    const float* h1pw = (const float*)d_in[8];
    const float* h1pb = (const float*)d_in[9];
    const float* h1tw = (const float*)d_in[10];
    const float* h1tb = (const float*)d_in[11];
    const float* c2w  = (const float*)d_in[12];
    const float* c2b  = (const float*)d_in[13];
    const float* c2ws = (const float*)d_in[14];
    const float* c2bs = (const float*)d_in[15];
    const float* h2pw = (const float*)d_in[16];
    const float* h2pb = (const float*)d_in[17];
    const float* h2tw = (const float*)d_in[18];
    const float* h2tb = (const float*)d_in[19];
    float* out = (float*)d_out;

    int N = in_sizes[0] / Dn;
    int E = in_sizes[1];

    __nv_bfloat162* Sp;
    float *h1p, *g1p, *h2p;
    cudaGetSymbolAddress((void**)&Sp, g_S);
    cudaGetSymbolAddress((void**)&h1p, g_h1);
    cudaGetSymbolAddress((void**)&g1p, g_g1);
    cudaGetSymbolAddress((void**)&h2p, g_h2);

    const int convSmem = 320 * BSTR * 4 + 64 * 4;
    const int hwSmem   = 2 * 128 * BSTR * 4 + 128 * 4;
    cudaFuncSetAttribute(conv_mma_kernel, cudaFuncAttributeMaxDynamicSharedMemorySize, convSmem);
    cudaFuncSetAttribute(highway_mma_kernel, cudaFuncAttributeMaxDynamicSharedMemorySize, hwSmem);

    int convGrid = (N + 255) / 256;
    int hwGrid   = (N + 127) / 128;
    int scanBlocks = (SEGS + 1023) / 1024;

    // ---- CSR build (graph identical in both layers) ----
    zero_deg_kernel<<<(SEGS + 255) / 256, 256>>>();
    hist_kernel<<<(E + 255) / 256, 256>>>(dst, rel, E);
    scan1_kernel<<<scanBlocks, 1024>>>(SEGS);
    scan2_kernel<<<1, 512>>>(scanBlocks);
    scan3_kernel<<<(SEGS + 255) / 256, 256>>>(SEGS, E);
    scatter_kernel<<<(E + 255) / 256, 256>>>(src, dst, rel, E);

    int aggGrid = SEGS / 16;

    // ---- layer 1 ----
    aggregate_kernel<<<aggGrid, 256>>>(x);
    conv_mma_kernel<<<convGrid, 256, convSmem>>>(x, Sp, c1w, c1b, c1ws, c1bs, h1p, N);
    highway_mma_kernel<<<hwGrid, 256, hwSmem>>>(h1p, x, h1pw, h1pb, h1tw, h1tb, g1p, N);

    // ---- layer 2 ----
    aggregate_kernel<<<aggGrid, 256>>>(g1p);
    conv_mma_kernel<<<convGrid, 256, convSmem>>>(g1p, Sp, c2w, c2b, c2ws, c2bs, h2p, N);
    highway_mma_kernel<<<hwGrid, 256, hwSmem>>>(h2p, h1p, h2pw, h2pb, h2tw, h2tb, out, N);
}